// round 4
// baseline (speedup 1.0000x reference)
#include <cuda_runtime.h>
#include <cuda_bf16.h>

// L, R: [N, C, H, W] fp32 ; out: [N, C, D, H, W] fp32
// out[n,c,d,h,w] = (w >= d) ? L[n,c,h,w] - R[n,c,h,w-d] : 1.0f
static constexpr int Nn = 2;
static constexpr int Cc = 32;
static constexpr int Hh = 128;
static constexpr int Ww = 256;
static constexpr int Dd = 48;

static constexpr int W4   = Ww / 4;        // 64 float4 per row
static constexpr int NCH  = Nn * Cc * Hh;  // 8192 rows
static constexpr int HW   = Hh * Ww;
static constexpr int HW4  = HW / 4;        // float4 stride between d planes

// Full R window a thread needs across all 48 disparities:
// r[w-48 .. w+3] -> 13 aligned float4 (52 floats). win[0] is slack.
static constexpr int WINF4 = 13;

__global__ __launch_bounds__(256)
void cost_volume_kernel(const float* __restrict__ L,
                        const float* __restrict__ R,
                        float* __restrict__ out)
{
    int tid = blockIdx.x * 256 + threadIdx.x;   // exact grid: NCH*W4 threads
    int w4  = tid & (W4 - 1);                   // 0..63
    int row = tid >> 6;                         // 0..8191
    int h   = row & (Hh - 1);
    int nc  = row >> 7;

    int w = w4 * 4;

    const float4* __restrict__ rrow4 =
        reinterpret_cast<const float4*>(R + (size_t)row * Ww);

    // L operand: one LDG.128, reused for all 48 disparities.
    float4 lv = __ldg(reinterpret_cast<const float4*>(L + (size_t)row * Ww) + w4);

    // Entire R window up front: 13 aligned vector loads, issued back-to-back
    // (high MLP, one latency exposure). Clamped indices produce garbage that
    // the (w>=d) predicate masks to 1.0.
    float win[4 * WINF4];
    #pragma unroll
    for (int j = 0; j < WINF4; ++j) {
        int idx = w4 - (WINF4 - 1) + j;         // w4-12 .. w4
        idx = idx < 0 ? 0 : idx;
        float4 v = __ldg(rrow4 + idx);
        win[4 * j + 0] = v.x;
        win[4 * j + 1] = v.y;
        win[4 * j + 2] = v.z;
        win[4 * j + 3] = v.w;
    }

    float4* outp = reinterpret_cast<float4*>(
        out + ((size_t)(nc * Dd) * Hh + h) * (size_t)Ww + w);

    // win[0] holds float index w-48, so r[w+k-d] = win[48 + k - d].
    // All indices are compile-time constants after unrolling; the 48 stores
    // form one unbroken independent stream.
    #pragma unroll
    for (int d = 0; d < Dd; ++d) {
        float4 o;
        o.x = (w + 0 >= d) ? (lv.x - win[48 + 0 - d]) : 1.0f;
        o.y = (w + 1 >= d) ? (lv.y - win[48 + 1 - d]) : 1.0f;
        o.z = (w + 2 >= d) ? (lv.z - win[48 + 2 - d]) : 1.0f;
        o.w = (w + 3 >= d) ? (lv.w - win[48 + 3 - d]) : 1.0f;
        __stcs(outp + (size_t)d * HW4, o);      // streaming STG.128, evict-first
    }
}

extern "C" void kernel_launch(void* const* d_in, const int* in_sizes, int n_in,
                              void* d_out, int out_size)
{
    const float* L = (const float*)d_in[0];
    const float* R = (const float*)d_in[1];
    float* out = (float*)d_out;

    const int total_threads = NCH * W4;       // 524,288
    const int block = 256;
    const int grid  = total_threads / block;  // 2048
    cost_volume_kernel<<<grid, block>>>(L, R, out);
}

// round 5
// speedup vs baseline: 1.3121x; 1.3121x over previous
#include <cuda_runtime.h>
#include <cuda_bf16.h>

// L, R: [N, C, H, W] fp32 ; out: [N, C, D, H, W] fp32
// out[n,c,d,h,w] = (w >= d) ? L[n,c,h,w] - R[n,c,h,w-d] : 1.0f
static constexpr int Nn = 2;
static constexpr int Cc = 32;
static constexpr int Hh = 128;
static constexpr int Ww = 256;
static constexpr int Dd = 48;

static constexpr int W4   = Ww / 4;        // 64 float4 per row
static constexpr int NCH  = Nn * Cc * Hh;  // 8192 rows
static constexpr int HW   = Hh * Ww;
static constexpr int HW4  = HW / 4;        // float4 stride between d planes

static constexpr int ROWS_PER_BLOCK = 4;   // 256 threads = 4 rows x 64 w4

__global__ __launch_bounds__(256)
void cost_volume_kernel(const float* __restrict__ L,
                        const float* __restrict__ R,
                        float* __restrict__ out)
{
    // Shared staging of 4 R rows: 4 x 256 floats = 4 KB.
    __shared__ float4 rsh[ROWS_PER_BLOCK][W4];

    const int tid  = threadIdx.x;
    const int w4   = tid & (W4 - 1);           // 0..63
    const int rin  = tid >> 6;                 // row within block, 0..3
    const int row  = blockIdx.x * ROWS_PER_BLOCK + rin;  // 0..8191
    const int h    = row & (Hh - 1);
    const int nc   = row >> 7;
    const int w    = w4 * 4;

    // Stage R row into shared (coalesced, one float4 per thread) and grab L.
    rsh[rin][w4] = __ldg(reinterpret_cast<const float4*>(R + (size_t)row * Ww) + w4);
    float4 lv    = __ldg(reinterpret_cast<const float4*>(L + (size_t)row * Ww) + w4);
    __syncthreads();

    float4* outp = reinterpret_cast<float4*>(
        out + ((size_t)(nc * Dd) * Hh + h) * (size_t)Ww + w);

    // Sliding 8-float window over the shared R row.
    // Group g handles d = 4g..4g+3 and needs r[w-4g-4 .. w+3-4g]:
    //   low  = rsh[rin][w4-g-1] (clamped), high = previous group's low.
    float4 hi = rsh[rin][w4];                  // r[w .. w+3]

    #pragma unroll
    for (int g = 0; g < Dd / 4; ++g) {
        int jl = w4 - g - 1;
        jl = jl < 0 ? 0 : jl;                  // clamp; garbage masked by (w>=d)
        float4 lo = rsh[rin][jl];

        // Combined window win[0..7] = {lo.x..lo.w, hi.x..hi.w}
        //   = r[w-4g-4 .. w-4g+3]; r[w+k-d] with d=4g+dd -> win[4 + k - dd].
        float win[8];
        win[0] = lo.x; win[1] = lo.y; win[2] = lo.z; win[3] = lo.w;
        win[4] = hi.x; win[5] = hi.y; win[6] = hi.z; win[7] = hi.w;

        #pragma unroll
        for (int dd = 0; dd < 4; ++dd) {
            const int d = 4 * g + dd;
            float4 o;
            o.x = (w + 0 >= d) ? (lv.x - win[4 + 0 - dd]) : 1.0f;
            o.y = (w + 1 >= d) ? (lv.y - win[4 + 1 - dd]) : 1.0f;
            o.z = (w + 2 >= d) ? (lv.z - win[4 + 2 - dd]) : 1.0f;
            o.w = (w + 3 >= d) ? (lv.w - win[4 + 3 - dd]) : 1.0f;
            __stcs(outp + (size_t)d * HW4, o); // streaming STG.128, evict-first
        }

        hi = lo;                               // slide window left by 4
    }
}

extern "C" void kernel_launch(void* const* d_in, const int* in_sizes, int n_in,
                              void* d_out, int out_size)
{
    const float* L = (const float*)d_in[0];
    const float* R = (const float*)d_in[1];
    float* out = (float*)d_out;

    const int block = 256;
    const int grid  = NCH / ROWS_PER_BLOCK;   // 2048 blocks, exact
    cost_volume_kernel<<<grid, block>>>(L, R, out);
}